// round 6
// baseline (speedup 1.0000x reference)
#include <cuda_runtime.h>
#include <cstdint>

#define N_NODES 50000
#define F_IN    1024
#define F_HID   256
#define F_OUT   256
#define EPS     1e-5f
#define E_MAX   1048576
#define NB_SCAN 196        // ceil(50000/256)

// ---------------- scratch (allocation-free: device globals) ----------------
__device__ __align__(256) float g_h[(size_t)N_NODES * F_HID];
__device__ __align__(256) float g_agg[(size_t)N_NODES * F_HID];
__device__ float g_deg[N_NODES];
__device__ float g_dinv[N_NODES];
__device__ int   g_cnt[N_NODES];
__device__ int   g_offs[N_NODES];
__device__ int   g_cursor[N_NODES];
__device__ int   g_chunk[256];
__device__ int   g_chunkbase[256];
__device__ int   g_csr_src[E_MAX];
__device__ float g_csr_w[E_MAX];
__device__ float g_colsum[F_OUT];
__device__ float g_colsumsq[F_OUT];

// ---------------- init / degree / histogram ----------------
__global__ void k_init() {
    int i = blockIdx.x * blockDim.x + threadIdx.x;
    if (i < N_NODES) { g_deg[i] = 1.0f; g_cnt[i] = 0; g_cursor[i] = 0; }
    if (i < F_OUT)   { g_colsum[i] = 0.f; g_colsumsq[i] = 0.f; }
}

// edge_index is int32 on device (JAX x64 disabled downcasts int64).
__global__ void k_deg_hist(const int* __restrict__ ei,
                           const float* __restrict__ ew, int E) {
    int e = blockIdx.x * blockDim.x + threadIdx.x;
    if (e >= E) return;
    int d = ei[E + e];
    atomicAdd(&g_deg[d], ew[e]);
    atomicAdd(&g_cnt[d], 1);
}

// ---------------- scan (+ dinv fused into pass 1) ----------------
__global__ void k_scan1() {
    __shared__ int sm[256];
    int tid = threadIdx.x;
    int i = blockIdx.x * 256 + tid;
    int v = (i < N_NODES) ? g_cnt[i] : 0;
    sm[tid] = v;
    __syncthreads();
    for (int o = 1; o < 256; o <<= 1) {
        int t = (tid >= o) ? sm[tid - o] : 0;
        __syncthreads();
        sm[tid] += t;
        __syncthreads();
    }
    if (i < N_NODES) {
        g_offs[i] = sm[tid] - v;
        g_dinv[i] = rsqrtf(g_deg[i]);   // deg >= 1 (self loop)
    }
    if (tid == 255) g_chunk[blockIdx.x] = sm[tid];
}

__global__ void k_scan2() {
    __shared__ int sm[256];
    int tid = threadIdx.x;
    int v = (tid < NB_SCAN) ? g_chunk[tid] : 0;
    sm[tid] = v;
    __syncthreads();
    for (int o = 1; o < 256; o <<= 1) {
        int t = (tid >= o) ? sm[tid - o] : 0;
        __syncthreads();
        sm[tid] += t;
        __syncthreads();
    }
    if (tid < NB_SCAN) g_chunkbase[tid] = sm[tid] - v;
}

__global__ void k_scan3() {
    int i = blockIdx.x * blockDim.x + threadIdx.x;
    if (i < N_NODES) g_offs[i] += g_chunkbase[i >> 8];
}

// ---------------- CSR fill (by destination) ----------------
__global__ void k_fill(const int* __restrict__ ei,
                       const float* __restrict__ ew, int E) {
    int e = blockIdx.x * blockDim.x + threadIdx.x;
    if (e >= E) return;
    int s = ei[e];
    int d = ei[E + e];
    int slot = g_offs[d] + atomicAdd(&g_cursor[d], 1);
    g_csr_src[slot] = s;
    g_csr_w[slot] = g_dinv[s] * ew[e] * g_dinv[d];
}

// ---------------- tf32 tensor-core GEMM ----------------
// C[M,N] = A[M,K] @ B[K,N], row-major. BM=256, BN=128, BK=32, 256 threads.
// Warp grid 4(M) x 2(N); warp tile 64x64 via m16n8k8 (4 mt x 8 nt).
// cp.async double-buffered; cvt.rna on fragment load (unbiased tf32).

__device__ __forceinline__ uint32_t tf32of(float x) {
    uint32_t y;
    asm("cvt.rna.tf32.f32 %0, %1;" : "=r"(y) : "f"(x));
    return y;
}

__device__ __forceinline__ void mma_tf32(float* c, const uint32_t* a, const uint32_t* b) {
    asm volatile(
        "mma.sync.aligned.m16n8k8.row.col.f32.tf32.tf32.f32 "
        "{%0,%1,%2,%3}, {%4,%5,%6,%7}, {%8,%9}, {%0,%1,%2,%3};"
        : "+f"(c[0]), "+f"(c[1]), "+f"(c[2]), "+f"(c[3])
        : "r"(a[0]), "r"(a[1]), "r"(a[2]), "r"(a[3]), "r"(b[0]), "r"(b[1]));
}

__device__ __forceinline__ void cp_async16(uint32_t dst, const void* src, int src_sz) {
    asm volatile("cp.async.cg.shared.global [%0], [%1], 16, %2;"
                 :: "r"(dst), "l"(src), "r"(src_sz));
}

#define AS_PAD 36   // (4g+q)%32 conflict-free fragment reads
#define BS_PAD 136  // (8q+g)%32 conflict-free fragment reads

__global__ __launch_bounds__(256) void k_tf32gemm(
    const float* __restrict__ A, const float* __restrict__ B,
    float* __restrict__ C, int M, int K, int N) {
    __shared__ float As[2][256][AS_PAD];   // 72 KB
    __shared__ float Bs[2][32][BS_PAD];    // 34 KB

    const int tid  = threadIdx.x;
    const int bm   = blockIdx.y * 256;
    const int bn   = blockIdx.x * 128;
    const int warp = tid >> 5;
    const int lane = tid & 31;
    const int wm   = warp >> 1;        // 0..3
    const int wn   = warp & 1;         // 0..1
    const int g    = lane >> 2;        // 0..7
    const int q    = lane & 3;         // 0..3

    float c[4][8][4] = {};

    auto load_tiles = [&](int stage, int k0) {
        #pragma unroll
        for (int i = 0; i < 8; i++) {                  // A: 256x32 floats
            int idx = i * 256 + tid;                   // 0..2047 float4 slots
            int row = idx >> 3;                        // 0..255
            int c4  = (idx & 7) << 2;
            int grow = bm + row;
            int ok = (grow < M) ? 16 : 0;
            const float* src = A + (size_t)(ok ? grow : 0) * K + k0 + c4;
            cp_async16((uint32_t)__cvta_generic_to_shared(&As[stage][row][c4]), src, ok);
        }
        #pragma unroll
        for (int i = 0; i < 4; i++) {                  // B: 32x128 floats
            int idx = i * 256 + tid;                   // 0..1023
            int row = idx >> 5;                        // 0..31
            int c4  = (idx & 31) << 2;                 // 0..124
            const float* src = B + (size_t)(k0 + row) * N + bn + c4;
            cp_async16((uint32_t)__cvta_generic_to_shared(&Bs[stage][row][c4]), src, 16);
        }
        asm volatile("cp.async.commit_group;");
    };

    const int nk = K >> 5;
    load_tiles(0, 0);
    asm volatile("cp.async.wait_group 0;");
    __syncthreads();

    int stage = 0;
    for (int kt = 0; kt < nk; kt++) {
        if (kt + 1 < nk) load_tiles(stage ^ 1, (kt + 1) << 5);

        #pragma unroll
        for (int s = 0; s < 4; s++) {
            const int k = s << 3;
            uint32_t af[4][4], bf[8][2];
            #pragma unroll
            for (int mt = 0; mt < 4; mt++) {
                int r0 = wm * 64 + mt * 16 + g;
                af[mt][0] = tf32of(As[stage][r0    ][k + q]);
                af[mt][1] = tf32of(As[stage][r0 + 8][k + q]);
                af[mt][2] = tf32of(As[stage][r0    ][k + q + 4]);
                af[mt][3] = tf32of(As[stage][r0 + 8][k + q + 4]);
            }
            #pragma unroll
            for (int nt = 0; nt < 8; nt++) {
                int c0 = wn * 64 + nt * 8 + g;
                bf[nt][0] = tf32of(Bs[stage][k + q    ][c0]);
                bf[nt][1] = tf32of(Bs[stage][k + q + 4][c0]);
            }
            #pragma unroll
            for (int mt = 0; mt < 4; mt++)
                #pragma unroll
                for (int nt = 0; nt < 8; nt++)
                    mma_tf32(c[mt][nt], af[mt], bf[nt]);
        }

        asm volatile("cp.async.wait_group 0;");
        __syncthreads();
        stage ^= 1;
    }

    #pragma unroll
    for (int mt = 0; mt < 4; mt++) {
        int row0 = bm + wm * 64 + mt * 16 + g;
        #pragma unroll
        for (int nt = 0; nt < 8; nt++) {
            int col = bn + wn * 64 + nt * 8 + 2 * q;
            if (row0 < M)
                *reinterpret_cast<float2*>(C + (size_t)row0 * N + col) =
                    make_float2(c[mt][nt][0], c[mt][nt][1]);
            if (row0 + 8 < M)
                *reinterpret_cast<float2*>(C + (size_t)(row0 + 8) * N + col) =
                    make_float2(c[mt][nt][2], c[mt][nt][3]);
        }
    }
}

// ---------------- CSR SpMM: warp per dst node, no atomics ----------------
// out[d,:] = dinv[d]^2 * h[d,:] + sum_e w_e * h[src_e,:]
// RELU:  v = relu(v + bias) epilogue (layer 1 -> b1).
// FINAL: v = relu(v + bias), plus fused BN column-stat accumulation (layer 2 -> b2).
// grid is exactly N_NODES/8 blocks (50000 % 8 == 0): no ragged warps.
template<bool RELU, bool FINAL>
__global__ __launch_bounds__(256) void k_spmm(
    const float* __restrict__ h, float* __restrict__ out,
    const float* __restrict__ bias) {
    __shared__ float ssum[F_OUT], ssq[F_OUT];
    if (FINAL) {
        ssum[threadIdx.x] = 0.f;
        ssq[threadIdx.x]  = 0.f;
        __syncthreads();
    }
    int node = blockIdx.x * 8 + (threadIdx.x >> 5);
    int lane = threadIdx.x & 31;

    const float4* hrow = reinterpret_cast<const float4*>(h + (size_t)node * F_HID);
    float dd = g_dinv[node]; dd = dd * dd;
    float4 v0 = hrow[lane], v1 = hrow[lane + 32];
    float4 a0 = make_float4(v0.x * dd, v0.y * dd, v0.z * dd, v0.w * dd);
    float4 a1 = make_float4(v1.x * dd, v1.y * dd, v1.z * dd, v1.w * dd);

    int beg = g_offs[node];
    int end = beg + g_cnt[node];
    for (int k = beg; k < end; k++) {
        int s   = g_csr_src[k];
        float w = g_csr_w[k];
        const float4* sr = reinterpret_cast<const float4*>(h + (size_t)s * F_HID);
        float4 s0 = sr[lane], s1 = sr[lane + 32];
        a0.x = fmaf(w, s0.x, a0.x); a0.y = fmaf(w, s0.y, a0.y);
        a0.z = fmaf(w, s0.z, a0.z); a0.w = fmaf(w, s0.w, a0.w);
        a1.x = fmaf(w, s1.x, a1.x); a1.y = fmaf(w, s1.y, a1.y);
        a1.z = fmaf(w, s1.z, a1.z); a1.w = fmaf(w, s1.w, a1.w);
    }
    if (RELU || FINAL) {
        const float4* b4 = reinterpret_cast<const float4*>(bias);
        float4 bb0 = b4[lane], bb1 = b4[lane + 32];
        a0.x = fmaxf(a0.x + bb0.x, 0.f); a0.y = fmaxf(a0.y + bb0.y, 0.f);
        a0.z = fmaxf(a0.z + bb0.z, 0.f); a0.w = fmaxf(a0.w + bb0.w, 0.f);
        a1.x = fmaxf(a1.x + bb1.x, 0.f); a1.y = fmaxf(a1.y + bb1.y, 0.f);
        a1.z = fmaxf(a1.z + bb1.z, 0.f); a1.w = fmaxf(a1.w + bb1.w, 0.f);
    }
    float4* op = reinterpret_cast<float4*>(out + (size_t)node * F_HID);
    op[lane]      = a0;
    op[lane + 32] = a1;

    if (FINAL) {
        int f0 = 4 * lane, f1 = 128 + 4 * lane;
        atomicAdd(&ssum[f0 + 0], a0.x); atomicAdd(&ssq[f0 + 0], a0.x * a0.x);
        atomicAdd(&ssum[f0 + 1], a0.y); atomicAdd(&ssq[f0 + 1], a0.y * a0.y);
        atomicAdd(&ssum[f0 + 2], a0.z); atomicAdd(&ssq[f0 + 2], a0.z * a0.z);
        atomicAdd(&ssum[f0 + 3], a0.w); atomicAdd(&ssq[f0 + 3], a0.w * a0.w);
        atomicAdd(&ssum[f1 + 0], a1.x); atomicAdd(&ssq[f1 + 0], a1.x * a1.x);
        atomicAdd(&ssum[f1 + 1], a1.y); atomicAdd(&ssq[f1 + 1], a1.y * a1.y);
        atomicAdd(&ssum[f1 + 2], a1.z); atomicAdd(&ssq[f1 + 2], a1.z * a1.z);
        atomicAdd(&ssum[f1 + 3], a1.w); atomicAdd(&ssq[f1 + 3], a1.w * a1.w);
        __syncthreads();
        atomicAdd(&g_colsum[threadIdx.x],   ssum[threadIdx.x]);
        atomicAdd(&g_colsumsq[threadIdx.x], ssq[threadIdx.x]);
    }
}

// ---------------- final: BN -> LN, in place; warp per row ----------------
// Input already has bias+relu applied (by spmm FINAL epilogue).
__global__ __launch_bounds__(256) void k_bn_ln(
    float* __restrict__ out,
    const float* __restrict__ bng, const float* __restrict__ bnb,
    const float* __restrict__ lng, const float* __restrict__ lnb) {
    int row  = (int)((blockIdx.x * 256u + threadIdx.x) >> 5);
    int lane = threadIdx.x & 31;
    if (row >= N_NODES) return;
    float* rowp = out + (size_t)row * F_OUT;
    const float invN = 1.0f / (float)N_NODES;
    float y[8];
    float s = 0.f, s2 = 0.f;
    #pragma unroll
    for (int j = 0; j < 8; j++) {
        int f = lane + 32 * j;
        float v   = rowp[f];
        float mu  = g_colsum[f] * invN;
        float var = g_colsumsq[f] * invN - mu * mu;
        float yy  = (v - mu) * rsqrtf(var + EPS) * bng[f] + bnb[f];
        y[j] = yy;
        s += yy; s2 += yy * yy;
    }
    #pragma unroll
    for (int o = 16; o; o >>= 1) {
        s  += __shfl_xor_sync(0xffffffffu, s, o);
        s2 += __shfl_xor_sync(0xffffffffu, s2, o);
    }
    float m   = s * (1.0f / F_OUT);
    float var = s2 * (1.0f / F_OUT) - m * m;
    float r   = rsqrtf(var + EPS);
    #pragma unroll
    for (int j = 0; j < 8; j++) {
        int f = lane + 32 * j;
        rowp[f] = (y[j] - m) * r * lng[f] + lnb[f];
    }
}

// ---------------- launch ----------------
extern "C" void kernel_launch(void* const* d_in, const int* in_sizes, int n_in,
                              void* d_out, int out_size) {
    const float* x   = (const float*)d_in[0];
    const int*   ei  = (const int*)d_in[1];     // int32 (JAX x64 disabled)
    const float* ew  = (const float*)d_in[2];
    const float* W1  = (const float*)d_in[3];
    const float* b1  = (const float*)d_in[4];
    const float* W2  = (const float*)d_in[5];
    const float* b2  = (const float*)d_in[6];
    const float* bng = (const float*)d_in[7];
    const float* bnb = (const float*)d_in[8];
    const float* lng = (const float*)d_in[9];
    const float* lnb = (const float*)d_in[10];
    float* out = (float*)d_out;
    const int E = in_sizes[2];

    float *hbuf, *abuf;
    cudaGetSymbolAddress((void**)&hbuf, g_h);
    cudaGetSymbolAddress((void**)&abuf, g_agg);

    const int T = 256;
    // prep (GEMM1 placed as 6th launch so ncu -s 5 -c 1 profiles it)
    k_init<<<(N_NODES + T - 1) / T, T>>>();          // 1
    k_deg_hist<<<(E + T - 1) / T, T>>>(ei, ew, E);   // 2
    k_scan1<<<NB_SCAN, 256>>>();                     // 3 (+dinv)
    k_scan2<<<1, 256>>>();                           // 4
    k_scan3<<<(N_NODES + T - 1) / T, T>>>();         // 5

    // layer 1 GEMM: h1 = x @ W1                     // 6  <-- profiled
    {
        dim3 grid(F_HID / 128, (N_NODES + 255) / 256);
        k_tf32gemm<<<grid, 256>>>(x, W1, hbuf, N_NODES, F_IN, F_HID);
    }
    k_fill<<<(E + T - 1) / T, T>>>(ei, ew, E);       // 7

    // agg1 = relu(D^-1/2 (A+I) D^-1/2 h1 + b1)
    k_spmm<true, false><<<N_NODES / 8, 256>>>(hbuf, abuf, b1);   // 8

    // layer 2 GEMM: h2 = agg1 @ W2
    {
        dim3 grid(F_OUT / 128, (N_NODES + 255) / 256);
        k_tf32gemm<<<grid, 256>>>(abuf, W2, hbuf, N_NODES, F_HID, F_OUT);  // 9
    }
    // agg2 + bias + relu + BN stats fused, into d_out
    k_spmm<false, true><<<N_NODES / 8, 256>>>(hbuf, out, b2);    // 10

    // BN apply + LN, in place
    k_bn_ln<<<(N_NODES + 7) / 8, 256>>>(out, bng, bnb, lng, lnb); // 11
}

// round 7
// speedup vs baseline: 1.0488x; 1.0488x over previous
#include <cuda_runtime.h>
#include <cstdint>

#define N_NODES 50000
#define F_IN    1024
#define F_HID   256
#define F_OUT   256
#define EPS     1e-5f
#define E_MAX   1048576
#define NB_SCAN 196        // ceil(50000/256)

// ---------------- scratch (allocation-free: device globals) ----------------
__device__ __align__(256) float g_h[(size_t)N_NODES * F_HID];
__device__ __align__(256) float g_agg[(size_t)N_NODES * F_HID];
__device__ float g_deg[N_NODES];
__device__ float g_dinv[N_NODES];
__device__ int   g_cnt[N_NODES];
__device__ int   g_offs[N_NODES];
__device__ int   g_cursor[N_NODES];
__device__ int   g_chunk[256];
__device__ int   g_chunkbase[256];
__device__ int   g_csr_src[E_MAX];
__device__ float g_csr_w[E_MAX];
__device__ float g_colsum[F_OUT];
__device__ float g_colsumsq[F_OUT];

// ---------------- init / degree / histogram ----------------
__global__ void k_init() {
    int i = blockIdx.x * blockDim.x + threadIdx.x;
    if (i < N_NODES) { g_deg[i] = 1.0f; g_cnt[i] = 0; g_cursor[i] = 0; }
    if (i < F_OUT)   { g_colsum[i] = 0.f; g_colsumsq[i] = 0.f; }
}

// edge_index is int32 on device (JAX x64 disabled downcasts int64).
__global__ void k_deg_hist(const int* __restrict__ ei,
                           const float* __restrict__ ew, int E) {
    int e = blockIdx.x * blockDim.x + threadIdx.x;
    if (e >= E) return;
    int d = ei[E + e];
    atomicAdd(&g_deg[d], ew[e]);
    atomicAdd(&g_cnt[d], 1);
}

// ---------------- scan (+ dinv fused into pass 1) ----------------
__global__ void k_scan1() {
    __shared__ int sm[256];
    int tid = threadIdx.x;
    int i = blockIdx.x * 256 + tid;
    int v = (i < N_NODES) ? g_cnt[i] : 0;
    sm[tid] = v;
    __syncthreads();
    for (int o = 1; o < 256; o <<= 1) {
        int t = (tid >= o) ? sm[tid - o] : 0;
        __syncthreads();
        sm[tid] += t;
        __syncthreads();
    }
    if (i < N_NODES) {
        g_offs[i] = sm[tid] - v;
        g_dinv[i] = rsqrtf(g_deg[i]);   // deg >= 1 (self loop)
    }
    if (tid == 255) g_chunk[blockIdx.x] = sm[tid];
}

__global__ void k_scan2() {
    __shared__ int sm[256];
    int tid = threadIdx.x;
    int v = (tid < NB_SCAN) ? g_chunk[tid] : 0;
    sm[tid] = v;
    __syncthreads();
    for (int o = 1; o < 256; o <<= 1) {
        int t = (tid >= o) ? sm[tid - o] : 0;
        __syncthreads();
        sm[tid] += t;
        __syncthreads();
    }
    if (tid < NB_SCAN) g_chunkbase[tid] = sm[tid] - v;
}

__global__ void k_scan3() {
    int i = blockIdx.x * blockDim.x + threadIdx.x;
    if (i < N_NODES) g_offs[i] += g_chunkbase[i >> 8];
}

// ---------------- CSR fill (by destination) ----------------
__global__ void k_fill(const int* __restrict__ ei,
                       const float* __restrict__ ew, int E) {
    int e = blockIdx.x * blockDim.x + threadIdx.x;
    if (e >= E) return;
    int s = ei[e];
    int d = ei[E + e];
    int slot = g_offs[d] + atomicAdd(&g_cursor[d], 1);
    g_csr_src[slot] = s;
    g_csr_w[slot] = g_dinv[s] * ew[e] * g_dinv[d];
}

// ---------------- tf32 tensor-core GEMM (round-5 proven config) ----------------
// C[M,N] = A[M,K] @ B[K,N], row-major. BM=128, BN=128, BK=32, 256 threads.
// Warp grid 2(M) x 4(N); warp tile 64x32 via m16n8k8 (4 mt x 4 nt).
// cp.async double-buffered; cvt.rna on fragment load (unbiased tf32).

__device__ __forceinline__ uint32_t tf32of(float x) {
    uint32_t y;
    asm("cvt.rna.tf32.f32 %0, %1;" : "=r"(y) : "f"(x));
    return y;
}

__device__ __forceinline__ void mma_tf32(float* c, const uint32_t* a, const uint32_t* b) {
    asm volatile(
        "mma.sync.aligned.m16n8k8.row.col.f32.tf32.tf32.f32 "
        "{%0,%1,%2,%3}, {%4,%5,%6,%7}, {%8,%9}, {%0,%1,%2,%3};"
        : "+f"(c[0]), "+f"(c[1]), "+f"(c[2]), "+f"(c[3])
        : "r"(a[0]), "r"(a[1]), "r"(a[2]), "r"(a[3]), "r"(b[0]), "r"(b[1]));
}

__device__ __forceinline__ void cp_async16(uint32_t dst, const void* src, int src_sz) {
    asm volatile("cp.async.cg.shared.global [%0], [%1], 16, %2;"
                 :: "r"(dst), "l"(src), "r"(src_sz));
}

#define AS_PAD 36   // (4g+q)%32 conflict-free fragment reads
#define BS_PAD 136  // (8q+g)%32 conflict-free fragment reads

__global__ __launch_bounds__(256) void k_tf32gemm(
    const float* __restrict__ A, const float* __restrict__ B,
    float* __restrict__ C, int M, int K, int N) {
    __shared__ float As[2][128][AS_PAD];
    __shared__ float Bs[2][32][BS_PAD];

    const int tid  = threadIdx.x;
    const int bm   = blockIdx.y * 128;
    const int bn   = blockIdx.x * 128;
    const int warp = tid >> 5;
    const int lane = tid & 31;
    const int wm   = warp >> 2;        // 0..1
    const int wn   = warp & 3;         // 0..3
    const int g    = lane >> 2;        // 0..7
    const int q    = lane & 3;         // 0..3

    float c[4][4][4] = {};

    auto load_tiles = [&](int stage, int k0) {
        #pragma unroll
        for (int i = 0; i < 4; i++) {
            int idx = i * 256 + tid;               // 0..1023
            int row = idx >> 3;
            int c4  = (idx & 7) << 2;
            int grow = bm + row;
            int ok = (grow < M) ? 16 : 0;
            const float* src = A + (size_t)(ok ? grow : 0) * K + k0 + c4;
            cp_async16((uint32_t)__cvta_generic_to_shared(&As[stage][row][c4]), src, ok);
        }
        #pragma unroll
        for (int i = 0; i < 4; i++) {
            int idx = i * 256 + tid;
            int row = idx >> 5;                    // 0..31
            int c4  = (idx & 31) << 2;             // 0..124
            const float* src = B + (size_t)(k0 + row) * N + bn + c4;
            cp_async16((uint32_t)__cvta_generic_to_shared(&Bs[stage][row][c4]), src, 16);
        }
        asm volatile("cp.async.commit_group;");
    };

    const int nk = K >> 5;
    load_tiles(0, 0);
    asm volatile("cp.async.wait_group 0;");
    __syncthreads();

    int stage = 0;
    for (int kt = 0; kt < nk; kt++) {
        if (kt + 1 < nk) load_tiles(stage ^ 1, (kt + 1) << 5);

        #pragma unroll
        for (int s = 0; s < 4; s++) {
            const int k = s << 3;
            uint32_t af[4][4], bf[4][2];
            #pragma unroll
            for (int mt = 0; mt < 4; mt++) {
                int r0 = wm * 64 + mt * 16 + g;
                af[mt][0] = tf32of(As[stage][r0    ][k + q]);
                af[mt][1] = tf32of(As[stage][r0 + 8][k + q]);
                af[mt][2] = tf32of(As[stage][r0    ][k + q + 4]);
                af[mt][3] = tf32of(As[stage][r0 + 8][k + q + 4]);
            }
            #pragma unroll
            for (int nt = 0; nt < 4; nt++) {
                int c0 = wn * 32 + nt * 8 + g;
                bf[nt][0] = tf32of(Bs[stage][k + q    ][c0]);
                bf[nt][1] = tf32of(Bs[stage][k + q + 4][c0]);
            }
            #pragma unroll
            for (int mt = 0; mt < 4; mt++)
                #pragma unroll
                for (int nt = 0; nt < 4; nt++)
                    mma_tf32(c[mt][nt], af[mt], bf[nt]);
        }

        asm volatile("cp.async.wait_group 0;");
        __syncthreads();
        stage ^= 1;
    }

    #pragma unroll
    for (int mt = 0; mt < 4; mt++) {
        int row0 = bm + wm * 64 + mt * 16 + g;
        #pragma unroll
        for (int nt = 0; nt < 4; nt++) {
            int col = bn + wn * 32 + nt * 8 + 2 * q;
            if (row0 < M)
                *reinterpret_cast<float2*>(C + (size_t)row0 * N + col) =
                    make_float2(c[mt][nt][0], c[mt][nt][1]);
            if (row0 + 8 < M)
                *reinterpret_cast<float2*>(C + (size_t)(row0 + 8) * N + col) =
                    make_float2(c[mt][nt][2], c[mt][nt][3]);
        }
    }
}

// ---------------- CSR SpMM: warp per dst node, no atomics ----------------
// out[d,:] = dinv[d]^2 * h[d,:] + sum_e w_e * h[src_e,:]
// RELU:  v = relu(v + bias) epilogue (layer 1 -> b1).
// FINAL: v = relu(v + bias) + fused BN column-stat accumulation (layer 2 -> b2).
// grid is exactly N_NODES/8 blocks (50000 % 8 == 0): no ragged warps.
template<bool RELU, bool FINAL>
__global__ __launch_bounds__(256) void k_spmm(
    const float* __restrict__ h, float* __restrict__ out,
    const float* __restrict__ bias) {
    __shared__ float ssum[F_OUT], ssq[F_OUT];
    if (FINAL) {
        ssum[threadIdx.x] = 0.f;
        ssq[threadIdx.x]  = 0.f;
        __syncthreads();
    }
    int node = blockIdx.x * 8 + (threadIdx.x >> 5);
    int lane = threadIdx.x & 31;

    const float4* hrow = reinterpret_cast<const float4*>(h + (size_t)node * F_HID);
    float dd = g_dinv[node]; dd = dd * dd;
    float4 v0 = hrow[lane], v1 = hrow[lane + 32];
    float4 a0 = make_float4(v0.x * dd, v0.y * dd, v0.z * dd, v0.w * dd);
    float4 a1 = make_float4(v1.x * dd, v1.y * dd, v1.z * dd, v1.w * dd);

    int beg = g_offs[node];
    int end = beg + g_cnt[node];
    for (int k = beg; k < end; k++) {
        int s   = g_csr_src[k];
        float w = g_csr_w[k];
        const float4* sr = reinterpret_cast<const float4*>(h + (size_t)s * F_HID);
        float4 s0 = sr[lane], s1 = sr[lane + 32];
        a0.x = fmaf(w, s0.x, a0.x); a0.y = fmaf(w, s0.y, a0.y);
        a0.z = fmaf(w, s0.z, a0.z); a0.w = fmaf(w, s0.w, a0.w);
        a1.x = fmaf(w, s1.x, a1.x); a1.y = fmaf(w, s1.y, a1.y);
        a1.z = fmaf(w, s1.z, a1.z); a1.w = fmaf(w, s1.w, a1.w);
    }
    if (RELU || FINAL) {
        const float4* b4 = reinterpret_cast<const float4*>(bias);
        float4 bb0 = b4[lane], bb1 = b4[lane + 32];
        a0.x = fmaxf(a0.x + bb0.x, 0.f); a0.y = fmaxf(a0.y + bb0.y, 0.f);
        a0.z = fmaxf(a0.z + bb0.z, 0.f); a0.w = fmaxf(a0.w + bb0.w, 0.f);
        a1.x = fmaxf(a1.x + bb1.x, 0.f); a1.y = fmaxf(a1.y + bb1.y, 0.f);
        a1.z = fmaxf(a1.z + bb1.z, 0.f); a1.w = fmaxf(a1.w + bb1.w, 0.f);
    }
    float4* op = reinterpret_cast<float4*>(out + (size_t)node * F_HID);
    op[lane]      = a0;
    op[lane + 32] = a1;

    if (FINAL) {
        int f0 = 4 * lane, f1 = 128 + 4 * lane;
        atomicAdd(&ssum[f0 + 0], a0.x); atomicAdd(&ssq[f0 + 0], a0.x * a0.x);
        atomicAdd(&ssum[f0 + 1], a0.y); atomicAdd(&ssq[f0 + 1], a0.y * a0.y);
        atomicAdd(&ssum[f0 + 2], a0.z); atomicAdd(&ssq[f0 + 2], a0.z * a0.z);
        atomicAdd(&ssum[f0 + 3], a0.w); atomicAdd(&ssq[f0 + 3], a0.w * a0.w);
        atomicAdd(&ssum[f1 + 0], a1.x); atomicAdd(&ssq[f1 + 0], a1.x * a1.x);
        atomicAdd(&ssum[f1 + 1], a1.y); atomicAdd(&ssq[f1 + 1], a1.y * a1.y);
        atomicAdd(&ssum[f1 + 2], a1.z); atomicAdd(&ssq[f1 + 2], a1.z * a1.z);
        atomicAdd(&ssum[f1 + 3], a1.w); atomicAdd(&ssq[f1 + 3], a1.w * a1.w);
        __syncthreads();
        atomicAdd(&g_colsum[threadIdx.x],   ssum[threadIdx.x]);
        atomicAdd(&g_colsumsq[threadIdx.x], ssq[threadIdx.x]);
    }
}

// ---------------- final: BN -> LN, in place; warp per row ----------------
__global__ __launch_bounds__(256) void k_bn_ln(
    float* __restrict__ out,
    const float* __restrict__ bng, const float* __restrict__ bnb,
    const float* __restrict__ lng, const float* __restrict__ lnb) {
    int row  = (int)((blockIdx.x * 256u + threadIdx.x) >> 5);
    int lane = threadIdx.x & 31;
    if (row >= N_NODES) return;
    float* rowp = out + (size_t)row * F_OUT;
    const float invN = 1.0f / (float)N_NODES;
    float y[8];
    float s = 0.f, s2 = 0.f;
    #pragma unroll
    for (int j = 0; j < 8; j++) {
        int f = lane + 32 * j;
        float v   = rowp[f];
        float mu  = g_colsum[f] * invN;
        float var = g_colsumsq[f] * invN - mu * mu;
        float yy  = (v - mu) * rsqrtf(var + EPS) * bng[f] + bnb[f];
        y[j] = yy;
        s += yy; s2 += yy * yy;
    }
    #pragma unroll
    for (int o = 16; o; o >>= 1) {
        s  += __shfl_xor_sync(0xffffffffu, s, o);
        s2 += __shfl_xor_sync(0xffffffffu, s2, o);
    }
    float m   = s * (1.0f / F_OUT);
    float var = s2 * (1.0f / F_OUT) - m * m;
    float r   = rsqrtf(var + EPS);
    #pragma unroll
    for (int j = 0; j < 8; j++) {
        int f = lane + 32 * j;
        rowp[f] = (y[j] - m) * r * lng[f] + lnb[f];
    }
}

// ---------------- launch ----------------
extern "C" void kernel_launch(void* const* d_in, const int* in_sizes, int n_in,
                              void* d_out, int out_size) {
    const float* x   = (const float*)d_in[0];
    const int*   ei  = (const int*)d_in[1];     // int32 (JAX x64 disabled)
    const float* ew  = (const float*)d_in[2];
    const float* W1  = (const float*)d_in[3];
    const float* b1  = (const float*)d_in[4];
    const float* W2  = (const float*)d_in[5];
    const float* b2  = (const float*)d_in[6];
    const float* bng = (const float*)d_in[7];
    const float* bnb = (const float*)d_in[8];
    const float* lng = (const float*)d_in[9];
    const float* lnb = (const float*)d_in[10];
    float* out = (float*)d_out;
    const int E = in_sizes[2];

    float *hbuf, *abuf;
    cudaGetSymbolAddress((void**)&hbuf, g_h);
    cudaGetSymbolAddress((void**)&abuf, g_agg);

    const int T = 256;
    // prep (GEMM1 placed as 6th launch so ncu -s 5 -c 1 profiles it)
    k_init<<<(N_NODES + T - 1) / T, T>>>();          // 1
    k_deg_hist<<<(E + T - 1) / T, T>>>(ei, ew, E);   // 2
    k_scan1<<<NB_SCAN, 256>>>();                     // 3 (+dinv)
    k_scan2<<<1, 256>>>();                           // 4
    k_scan3<<<(N_NODES + T - 1) / T, T>>>();         // 5

    // layer 1 GEMM: h1 = x @ W1                     // 6  <-- profiled
    {
        dim3 grid(F_HID / 128, (N_NODES + 127) / 128);
        k_tf32gemm<<<grid, 256>>>(x, W1, hbuf, N_NODES, F_IN, F_HID);
    }
    k_fill<<<(E + T - 1) / T, T>>>(ei, ew, E);       // 7

    // agg1 = relu(D^-1/2 (A+I) D^-1/2 h1 + b1)
    k_spmm<true, false><<<N_NODES / 8, 256>>>(hbuf, abuf, b1);   // 8

    // layer 2 GEMM: h2 = agg1 @ W2
    {
        dim3 grid(F_OUT / 128, (N_NODES + 127) / 128);
        k_tf32gemm<<<grid, 256>>>(abuf, W2, hbuf, N_NODES, F_HID, F_OUT);  // 9
    }
    // agg2 + bias + relu + BN stats fused, into d_out
    k_spmm<false, true><<<N_NODES / 8, 256>>>(hbuf, out, b2);    // 10

    // BN apply + LN, in place
    k_bn_ln<<<(N_NODES + 7) / 8, 256>>>(out, bng, bnb, lng, lnb); // 11
}